// round 5
// baseline (speedup 1.0000x reference)
#include <cuda_runtime.h>

// MediumLSTM: 2-layer LSTM (I=14, H=64, T=256, B=8192) + FC(64->64 relu)->FC(64->2)
// R5: 512 threads/CTA, 64 batch rows/CTA, grid=128 (single wave, 4 warps/SMSP).
// h0/h1 double-buffered in smem -> ONE __syncthreads per timestep (warps may skew,
// overlapping MUFU bursts with FMAs). w_hh0/w_hh1 gate-packed in smem; w_ih0/w_ih1
// gate-packed in global (L2-resident, shared by all CTAs). x pre-transposed to
// [t][i][b] so the hot loop reads it as broadcast 8B LDGs. Batch pairs packed into
// fma.rn.f32x2 (exact fp32 math). Fast sigmoid/tanh via __expf + __fdividef
// (MUFU.RCP — independent of -use_fast_math).

#define T_STEPS 256
#define HID     64
#define IN_F    14
#define BT      64      // batch rows per CTA
#define NP      4       // f32x2 pairs per thread (8 batch rows)
#define NTH     512
#define NGRID   128     // 8192 / BT

#define PADP    33      // h row stride in ull pairs (32 pairs + 1 pad)
#define PADF    66      // same in floats
#define HBUF    (HID * PADF)   // 4224 floats per h buffer

// shared memory float offsets
#define OFF_WHH0 0
#define OFF_WHH1 16384
#define OFF_H0A  32768
#define OFF_H0B  (OFF_H0A + HBUF)
#define OFF_H1A  (OFF_H0B + HBUF)
#define OFF_H1B  (OFF_H1A + HBUF)
#define SMEM_FLOATS (OFF_H1B + HBUF)       // 49664
#define SMEM_BYTES (SMEM_FLOATS * 4)        // 198,656 B

typedef unsigned long long ull;

// device scratch (allocation-free rule: __device__ globals)
__device__ float  g_xT[(size_t)T_STEPS * IN_F * 8192];   // [t][i][b]
__device__ float4 g_wih0p[IN_F * HID];                   // gate-packed w_ih0
__device__ float4 g_wih1p[HID * HID];                    // gate-packed w_ih1

__device__ __forceinline__ ull pk(float a, float b) {
    ull r;
    asm("mov.b64 %0, {%1,%2};" : "=l"(r) : "f"(a), "f"(b));
    return r;
}
__device__ __forceinline__ float2 upk(ull v) {
    float2 r;
    asm("mov.b64 {%0,%1}, %2;" : "=f"(r.x), "=f"(r.y) : "l"(v));
    return r;
}
__device__ __forceinline__ void fma2(ull &d, ull a, ull b) {
    asm("fma.rn.f32x2 %0, %1, %2, %0;" : "+l"(d) : "l"(a), "l"(b));
}
// sigmoid via EX2 + MUFU.RCP (flag-independent fast path)
__device__ __forceinline__ float sigf(float x) {
    return __fdividef(1.0f, 1.0f + __expf(-x));
}
// tanh(x) = 2/(1+exp(-2x)) - 1 ; saturates cleanly at +-1 for large |x|
__device__ __forceinline__ float tanhfast(float x) {
    return fmaf(2.0f, __fdividef(1.0f, 1.0f + __expf(-2.0f * x)), -1.0f);
}

// 64-wide hidden GEMM, weights in smem: acc[g][p] += Wp[k][u].g * h[k][pair]
__device__ __forceinline__ void gemm64s(const float4* __restrict__ w,
                                        const ull* __restrict__ hv,
                                        int u, int pb,
                                        ull* a0, ull* a1, ull* a2, ull* a3) {
#pragma unroll 8
    for (int k = 0; k < HID; k++) {
        float4 w4 = w[k * 64 + u];
        ull wi = pk(w4.x, w4.x);
        ull wf = pk(w4.y, w4.y);
        ull wg = pk(w4.z, w4.z);
        ull wo = pk(w4.w, w4.w);
#pragma unroll
        for (int p = 0; p < NP; p++) {
            ull h2 = hv[k * PADP + pb + p];
            fma2(a0[p], wi, h2);
            fma2(a1[p], wf, h2);
            fma2(a2[p], wg, h2);
            fma2(a3[p], wo, h2);
        }
    }
}

// 64-wide hidden GEMM, weights from global (L2-hot, coalesced LDG.128)
__device__ __forceinline__ void gemm64g(const float4* __restrict__ w,
                                        const ull* __restrict__ hv,
                                        int u, int pb,
                                        ull* a0, ull* a1, ull* a2, ull* a3) {
#pragma unroll 8
    for (int k = 0; k < HID; k++) {
        float4 w4 = __ldg(&w[k * 64 + u]);
        ull wi = pk(w4.x, w4.x);
        ull wf = pk(w4.y, w4.y);
        ull wg = pk(w4.z, w4.z);
        ull wo = pk(w4.w, w4.w);
#pragma unroll
        for (int p = 0; p < NP; p++) {
            ull h2 = hv[k * PADP + pb + p];
            fma2(a0[p], wi, h2);
            fma2(a1[p], wf, h2);
            fma2(a2[p], wg, h2);
            fma2(a3[p], wo, h2);
        }
    }
}

__device__ __forceinline__ void lstm_update(const ull* a0, const ull* a1,
                                            const ull* a2, const ull* a3,
                                            ull* cst, ull* hn) {
#pragma unroll
    for (int p = 0; p < NP; p++) {
        float2 gi = upk(a0[p]);
        float2 gf = upk(a1[p]);
        float2 gg = upk(a2[p]);
        float2 go = upk(a3[p]);
        float2 cc = upk(cst[p]);
        cc.x = sigf(gf.x) * cc.x + sigf(gi.x) * tanhfast(gg.x);
        cc.y = sigf(gf.y) * cc.y + sigf(gi.y) * tanhfast(gg.y);
        cst[p] = pk(cc.x, cc.y);
        hn[p] = pk(sigf(go.x) * tanhfast(cc.x), sigf(go.y) * tanhfast(cc.y));
    }
}

// ---------------- pre-kernels ----------------
__global__ void pack_wih_kernel(const float* __restrict__ w_ih0,
                                const float* __restrict__ w_ih1) {
    int n = blockIdx.x * blockDim.x + threadIdx.x;   // 0..4095
    if (n < IN_F * HID) {
        int i = n >> 6, u = n & 63;
        float4 v;
        v.x = w_ih0[(0 * 64 + u) * IN_F + i];
        v.y = w_ih0[(1 * 64 + u) * IN_F + i];
        v.z = w_ih0[(2 * 64 + u) * IN_F + i];
        v.w = w_ih0[(3 * 64 + u) * IN_F + i];
        g_wih0p[i * 64 + u] = v;
    }
    if (n < HID * HID) {
        int k = n >> 6, u = n & 63;
        float4 v;
        v.x = w_ih1[(0 * 64 + u) * HID + k];
        v.y = w_ih1[(1 * 64 + u) * HID + k];
        v.z = w_ih1[(2 * 64 + u) * HID + k];
        v.w = w_ih1[(3 * 64 + u) * HID + k];
        g_wih1p[k * 64 + u] = v;
    }
}

// x[b][ti] -> g_xT[ti][b], ti = t*14+i ; 3584 x 8192 transpose
__global__ void transpose_x_kernel(const float* __restrict__ x) {
    __shared__ float tile[32][33];
    int ti0 = blockIdx.x * 32;
    int b0  = blockIdx.y * 32;
    tile[threadIdx.y][threadIdx.x] =
        x[(size_t)(b0 + threadIdx.y) * (T_STEPS * IN_F) + ti0 + threadIdx.x];
    __syncthreads();
    g_xT[(size_t)(ti0 + threadIdx.y) * 8192 + b0 + threadIdx.x] =
        tile[threadIdx.x][threadIdx.y];
}

// ---------------- main fused kernel ----------------
__global__ void __launch_bounds__(NTH, 1)
lstm_fused_kernel(const float* __restrict__ w_hh0,
                  const float* __restrict__ b_ih0, const float* __restrict__ b_hh0,
                  const float* __restrict__ w_hh1,
                  const float* __restrict__ b_ih1, const float* __restrict__ b_hh1,
                  const float* __restrict__ w_fc1, const float* __restrict__ b_fc1,
                  const float* __restrict__ w_fc2, const float* __restrict__ b_fc2,
                  float* __restrict__ out) {
    extern __shared__ float sm[];
    const int tid = threadIdx.x;
    const int u  = tid & 63;   // hidden unit owned by this thread
    const int bg = tid >> 6;   // batch group (0..7), 8 rows each
    const int pb = bg * NP;    // pair base within a padded row
    const int b0 = blockIdx.x * BT;

    // ---- weights -> smem, transposed + gate-packed: Wp[k][u] = {Wi,Wf,Wg,Wo} at col k
    for (int n = tid; n < 256 * 64; n += NTH) {
        int j = n >> 6, k = n & 63;
        int g = j >> 6, uu = j & 63;
        int dst = (k * 64 + uu) * 4 + g;
        sm[OFF_WHH0 + dst] = w_hh0[n];
        sm[OFF_WHH1 + dst] = w_hh1[n];
    }
    // zero all four h buffers (contiguous region)
    for (int n = tid; n < 4 * HBUF; n += NTH) sm[OFF_H0A + n] = 0.0f;

    // biases (per-thread, per-gate), packed once
    ull bp0[4], bp1[4];
#pragma unroll
    for (int g = 0; g < 4; g++) {
        float v0 = b_ih0[g * 64 + u] + b_hh0[g * 64 + u];
        float v1 = b_ih1[g * 64 + u] + b_hh1[g * 64 + u];
        bp0[g] = pk(v0, v0);
        bp1[g] = pk(v1, v1);
    }
    __syncthreads();

    ull* h0buf[2] = { (ull*)(sm + OFF_H0A), (ull*)(sm + OFF_H0B) };
    ull* h1buf[2] = { (ull*)(sm + OFF_H1A), (ull*)(sm + OFF_H1B) };
    const float4* wHh0 = (const float4*)(sm + OFF_WHH0);
    const float4* wHh1 = (const float4*)(sm + OFF_WHH1);

    ull c0[NP], c1[NP];
#pragma unroll
    for (int p = 0; p < NP; p++) { c0[p] = 0ull; c1[p] = 0ull; }

    for (int t = 0; t < T_STEPS; t++) {
        const int cur = t & 1, nxt = cur ^ 1;
        ull* h0r = h0buf[cur];  ull* h0w = h0buf[nxt];
        ull* h1r = h1buf[cur];  ull* h1w = h1buf[nxt];

        // ================= layer 0 =================
        ull a0[NP], a1[NP], a2[NP], a3[NP];
#pragma unroll
        for (int p = 0; p < NP; p++) { a0[p] = bp0[0]; a1[p] = bp0[1]; a2[p] = bp0[2]; a3[p] = bp0[3]; }

        // input GEMM (14-wide) straight from L2: w from packed buffer (coalesced),
        // x from transposed layout (8B broadcast loads)
#pragma unroll
        for (int i = 0; i < IN_F; i++) {
            float4 w4 = __ldg(&g_wih0p[i * 64 + u]);
            const ull* xrow = (const ull*)(g_xT + (size_t)(t * IN_F + i) * 8192 + b0);
            ull wi = pk(w4.x, w4.x);
            ull wf = pk(w4.y, w4.y);
            ull wg = pk(w4.z, w4.z);
            ull wo = pk(w4.w, w4.w);
#pragma unroll
            for (int p = 0; p < NP; p++) {
                ull h2 = __ldg(&xrow[pb + p]);
                fma2(a0[p], wi, h2);
                fma2(a1[p], wf, h2);
                fma2(a2[p], wg, h2);
                fma2(a3[p], wo, h2);
            }
        }
        // hidden GEMM layer 0 (reads h0r, written two phases ago; ordered by sync of step t-1)
        gemm64s(wHh0, h0r, u, pb, a0, a1, a2, a3);

        ull hn[NP];
        lstm_update(a0, a1, a2, a3, c0, hn);

        // write new h0 into the OTHER buffer -> no pre-write barrier needed
#pragma unroll
        for (int p = 0; p < NP; p++) h0w[u * PADP + pb + p] = hn[p];

        __syncthreads();   // the ONLY barrier per timestep: h0w visible; also
                           // separates last step's h-buffer reads from upcoming reuse

        // ================= layer 1 =================
#pragma unroll
        for (int p = 0; p < NP; p++) { a0[p] = bp1[0]; a1[p] = bp1[1]; a2[p] = bp1[2]; a3[p] = bp1[3]; }
        gemm64g(g_wih1p, h0w, u, pb, a0, a1, a2, a3);   // input = new h0 (L2 weights)
        gemm64s(wHh1,    h1r, u, pb, a0, a1, a2, a3);   // recurrent = old h1 (smem weights)

        lstm_update(a0, a1, a2, a3, c1, hn);

        // write new h1 into the OTHER buffer; next step's layer-1 reads of it are
        // ordered by next step's barrier
#pragma unroll
        for (int p = 0; p < NP; p++) h1w[u * PADP + pb + p] = hn[p];
    }
    __syncthreads();       // final h1 writes visible for FC head

    // T_STEPS even -> last h1 written into h1buf[(255+1)&1] = h1buf[0]
    ull* h1f = h1buf[0];
    ull* zbuf = h0buf[0];  // reuse as z (different array than h1f -> no WAR)

    // ================= FC head =================
    // z[u][b] = relu(sum_k h1[b][k] * w_fc1[u][k] + b_fc1[u])
    {
        ull z[NP];
        float bb = b_fc1[u];
#pragma unroll
        for (int p = 0; p < NP; p++) z[p] = pk(bb, bb);
#pragma unroll 8
        for (int k = 0; k < HID; k++) {
            float w = w_fc1[u * HID + k];
            ull w2 = pk(w, w);
#pragma unroll
            for (int p = 0; p < NP; p++) fma2(z[p], w2, h1f[k * PADP + pb + p]);
        }
#pragma unroll
        for (int p = 0; p < NP; p++) {
            float2 zz = upk(z[p]);
            zz.x = fmaxf(zz.x, 0.0f);
            zz.y = fmaxf(zz.y, 0.0f);
            zbuf[u * PADP + pb + p] = pk(zz.x, zz.y);
        }
    }
    __syncthreads();

    // out[b][c] = sum_k z[k][b] * w_fc2[c][k] + b_fc2[c]
    if (tid < 128) {
        int b = tid & 63, c = tid >> 6;
        float acc = b_fc2[c];
#pragma unroll 8
        for (int k = 0; k < HID; k++) acc += sm[OFF_H0A + k * PADF + b] * w_fc2[c * HID + k];
        out[(size_t)(b0 + b) * 2 + c] = acc;
    }
}

extern "C" void kernel_launch(void* const* d_in, const int* in_sizes, int n_in,
                              void* d_out, int out_size) {
    const float* x     = (const float*)d_in[0];
    const float* w_ih0 = (const float*)d_in[1];
    const float* w_hh0 = (const float*)d_in[2];
    const float* b_ih0 = (const float*)d_in[3];
    const float* b_hh0 = (const float*)d_in[4];
    const float* w_ih1 = (const float*)d_in[5];
    const float* w_hh1 = (const float*)d_in[6];
    const float* b_ih1 = (const float*)d_in[7];
    const float* b_hh1 = (const float*)d_in[8];
    const float* w_fc1 = (const float*)d_in[9];
    const float* b_fc1 = (const float*)d_in[10];
    const float* w_fc2 = (const float*)d_in[11];
    const float* b_fc2 = (const float*)d_in[12];
    float* out = (float*)d_out;

    cudaFuncSetAttribute(lstm_fused_kernel,
                         cudaFuncAttributeMaxDynamicSharedMemorySize, SMEM_BYTES);

    pack_wih_kernel<<<8, 512>>>(w_ih0, w_ih1);
    {
        dim3 tb(32, 32);
        dim3 tg((T_STEPS * IN_F) / 32, 8192 / 32);   // 112 x 256
        transpose_x_kernel<<<tg, tb>>>(x);
    }
    lstm_fused_kernel<<<NGRID, NTH, SMEM_BYTES>>>(
        w_hh0, b_ih0, b_hh0,
        w_hh1, b_ih1, b_hh1,
        w_fc1, b_fc1, w_fc2, b_fc2, out);
}

// round 6
// speedup vs baseline: 1.3198x; 1.3198x over previous
#include <cuda_runtime.h>

// MediumLSTM: 2-layer LSTM (I=14, H=64, T=256, B=8192) + FC(64->64 relu)->FC(64->2)
// R6: 512 threads/CTA, 64 batch rows/CTA, grid=128 (single wave, 4 warps/SMSP).
// ALL three recurrent weight matrices (w_hh0, w_ih1, w_hh1) gate-packed fp32 in
// smem (192KB); h0/h1 single-buffered (16B-aligned rows -> merged LDS.128 loads);
// 3 barriers/timestep (R1-proven scheme). w_ih0 gate-packed in global (L1-hot,
// 14KB); x pre-transposed to [t][i][b] read as broadcast LDG.128 + L2 prefetch.
// Batch pairs packed into fma.rn.f32x2 (exact fp32 math). Fast sigmoid/tanh via
// __expf + __fdividef (MUFU, flag-independent).

#define T_STEPS 256
#define HID     64
#define IN_F    14
#define BT      64      // batch rows per CTA
#define NP      4       // f32x2 pairs per thread (8 batch rows)
#define NTH     512
#define NGRID   128     // 8192 / BT

#define PADP    34      // h row stride in ull pairs (32 pairs + 2 pad) -> 272B, 16B-aligned
#define PADF    68      // same in floats
#define HBUF    (HID * PADF)   // 4352 floats per h buffer

// shared memory float offsets
#define OFF_WHH0 0
#define OFF_WIH1 16384
#define OFF_WHH1 32768
#define OFF_H0   49152
#define OFF_H1   (OFF_H0 + HBUF)
#define SMEM_FLOATS (OFF_H1 + HBUF)        // 57856
#define SMEM_BYTES (SMEM_FLOATS * 4)        // 231,424 B

typedef unsigned long long ull;

// device scratch (allocation-free rule: __device__ globals)
__device__ float  g_xT[(size_t)T_STEPS * IN_F * 8192];   // [t][i][b]
__device__ float4 g_wih0p[IN_F * HID];                   // gate-packed w_ih0

__device__ __forceinline__ ull pk(float a, float b) {
    ull r;
    asm("mov.b64 %0, {%1,%2};" : "=l"(r) : "f"(a), "f"(b));
    return r;
}
__device__ __forceinline__ float2 upk(ull v) {
    float2 r;
    asm("mov.b64 {%0,%1}, %2;" : "=f"(r.x), "=f"(r.y) : "l"(v));
    return r;
}
__device__ __forceinline__ void fma2(ull &d, ull a, ull b) {
    asm("fma.rn.f32x2 %0, %1, %2, %0;" : "+l"(d) : "l"(a), "l"(b));
}
// sigmoid via EX2 + MUFU.RCP (flag-independent fast path)
__device__ __forceinline__ float sigf(float x) {
    return __fdividef(1.0f, 1.0f + __expf(-x));
}
// tanh(x) = 2/(1+exp(-2x)) - 1 ; saturates cleanly at +-1 for large |x|
__device__ __forceinline__ float tanhfast(float x) {
    return fmaf(2.0f, __fdividef(1.0f, 1.0f + __expf(-2.0f * x)), -1.0f);
}

// 64-wide hidden GEMM, weights+h in smem; h loads merged into 2x LDS.128 per k.
__device__ __forceinline__ void gemm64s(const float4* __restrict__ w,
                                        const ull* __restrict__ hv,
                                        int u, int pb,
                                        ull* a0, ull* a1, ull* a2, ull* a3) {
#pragma unroll 8
    for (int k = 0; k < HID; k++) {
        float4 w4 = w[k * 64 + u];
        ull wi = pk(w4.x, w4.x);
        ull wf = pk(w4.y, w4.y);
        ull wg = pk(w4.z, w4.z);
        ull wo = pk(w4.w, w4.w);
        ulonglong2 hA = *(const ulonglong2*)(hv + k * PADP + pb);
        ulonglong2 hB = *(const ulonglong2*)(hv + k * PADP + pb + 2);
        fma2(a0[0], wi, hA.x); fma2(a0[1], wi, hA.y); fma2(a0[2], wi, hB.x); fma2(a0[3], wi, hB.y);
        fma2(a1[0], wf, hA.x); fma2(a1[1], wf, hA.y); fma2(a1[2], wf, hB.x); fma2(a1[3], wf, hB.y);
        fma2(a2[0], wg, hA.x); fma2(a2[1], wg, hA.y); fma2(a2[2], wg, hB.x); fma2(a2[3], wg, hB.y);
        fma2(a3[0], wo, hA.x); fma2(a3[1], wo, hA.y); fma2(a3[2], wo, hB.x); fma2(a3[3], wo, hB.y);
    }
}

__device__ __forceinline__ void lstm_update(const ull* a0, const ull* a1,
                                            const ull* a2, const ull* a3,
                                            ull* cst, ull* hn) {
#pragma unroll
    for (int p = 0; p < NP; p++) {
        float2 gi = upk(a0[p]);
        float2 gf = upk(a1[p]);
        float2 gg = upk(a2[p]);
        float2 go = upk(a3[p]);
        float2 cc = upk(cst[p]);
        cc.x = sigf(gf.x) * cc.x + sigf(gi.x) * tanhfast(gg.x);
        cc.y = sigf(gf.y) * cc.y + sigf(gi.y) * tanhfast(gg.y);
        cst[p] = pk(cc.x, cc.y);
        hn[p] = pk(sigf(go.x) * tanhfast(cc.x), sigf(go.y) * tanhfast(cc.y));
    }
}

// ---------------- pre-kernels ----------------
__global__ void pack_wih0_kernel(const float* __restrict__ w_ih0) {
    int n = threadIdx.x;             // 0..895 : i*64 + u
    if (n < IN_F * HID) {
        int i = n >> 6, u = n & 63;
        float4 v;
        v.x = w_ih0[(0 * 64 + u) * IN_F + i];
        v.y = w_ih0[(1 * 64 + u) * IN_F + i];
        v.z = w_ih0[(2 * 64 + u) * IN_F + i];
        v.w = w_ih0[(3 * 64 + u) * IN_F + i];
        g_wih0p[i * 64 + u] = v;
    }
}

// x[b][ti] -> g_xT[ti][b], ti = t*14+i ; 3584 x 8192 transpose
__global__ void transpose_x_kernel(const float* __restrict__ x) {
    __shared__ float tile[32][33];
    int ti0 = blockIdx.x * 32;
    int b0  = blockIdx.y * 32;
    tile[threadIdx.y][threadIdx.x] =
        x[(size_t)(b0 + threadIdx.y) * (T_STEPS * IN_F) + ti0 + threadIdx.x];
    __syncthreads();
    g_xT[(size_t)(ti0 + threadIdx.y) * 8192 + b0 + threadIdx.x] =
        tile[threadIdx.x][threadIdx.y];
}

// ---------------- main fused kernel ----------------
__global__ void __launch_bounds__(NTH, 1)
lstm_fused_kernel(const float* __restrict__ w_hh0,
                  const float* __restrict__ b_ih0, const float* __restrict__ b_hh0,
                  const float* __restrict__ w_ih1, const float* __restrict__ w_hh1,
                  const float* __restrict__ b_ih1, const float* __restrict__ b_hh1,
                  const float* __restrict__ w_fc1, const float* __restrict__ b_fc1,
                  const float* __restrict__ w_fc2, const float* __restrict__ b_fc2,
                  float* __restrict__ out) {
    extern __shared__ float sm[];
    const int tid = threadIdx.x;
    const int u  = tid & 63;   // hidden unit owned by this thread
    const int bg = tid >> 6;   // batch group (0..7), 8 rows each
    const int pb = bg * NP;    // pair base within a padded row
    const int b0 = blockIdx.x * BT;

    // ---- weights -> smem, transposed + gate-packed: Wp[k][u] = {Wi,Wf,Wg,Wo} at col k
    for (int n = tid; n < 256 * 64; n += NTH) {
        int j = n >> 6, k = n & 63;
        int g = j >> 6, uu = j & 63;
        int dst = (k * 64 + uu) * 4 + g;
        sm[OFF_WHH0 + dst] = w_hh0[n];
        sm[OFF_WIH1 + dst] = w_ih1[n];
        sm[OFF_WHH1 + dst] = w_hh1[n];
    }
    // zero h0/h1 state (contiguous region)
    for (int n = tid; n < 2 * HBUF; n += NTH) sm[OFF_H0 + n] = 0.0f;

    // biases (per-thread, per-gate), packed once
    ull bp0[4], bp1[4];
#pragma unroll
    for (int g = 0; g < 4; g++) {
        float v0 = b_ih0[g * 64 + u] + b_hh0[g * 64 + u];
        float v1 = b_ih1[g * 64 + u] + b_hh1[g * 64 + u];
        bp0[g] = pk(v0, v0);
        bp1[g] = pk(v1, v1);
    }
    __syncthreads();

    ull* h0p = (ull*)(sm + OFF_H0);
    ull* h1p = (ull*)(sm + OFF_H1);
    const float4* wHh0 = (const float4*)(sm + OFF_WHH0);
    const float4* wIh1 = (const float4*)(sm + OFF_WIH1);
    const float4* wHh1 = (const float4*)(sm + OFF_WHH1);

    ull c0[NP], c1[NP];
#pragma unroll
    for (int p = 0; p < NP; p++) { c0[p] = 0ull; c1[p] = 0ull; }

    for (int t = 0; t < T_STEPS; t++) {
        // ================= layer 0 =================
        ull a0[NP], a1[NP], a2[NP], a3[NP];
#pragma unroll
        for (int p = 0; p < NP; p++) { a0[p] = bp0[0]; a1[p] = bp0[1]; a2[p] = bp0[2]; a3[p] = bp0[3]; }

        // input GEMM (14-wide): w from packed global (L1-hot), x from transposed
        // layout (broadcast LDG.128, streamed; prefetched one step ahead)
#pragma unroll
        for (int i = 0; i < IN_F; i++) {
            float4 w4 = __ldg(&g_wih0p[i * 64 + u]);
            const ull* xrow = (const ull*)(g_xT + (size_t)(t * IN_F + i) * 8192 + b0);
            ull wi = pk(w4.x, w4.x);
            ull wf = pk(w4.y, w4.y);
            ull wg = pk(w4.z, w4.z);
            ull wo = pk(w4.w, w4.w);
            ulonglong2 xA = *(const ulonglong2*)(xrow + pb);
            ulonglong2 xB = *(const ulonglong2*)(xrow + pb + 2);
            fma2(a0[0], wi, xA.x); fma2(a0[1], wi, xA.y); fma2(a0[2], wi, xB.x); fma2(a0[3], wi, xB.y);
            fma2(a1[0], wf, xA.x); fma2(a1[1], wf, xA.y); fma2(a1[2], wf, xB.x); fma2(a1[3], wf, xB.y);
            fma2(a2[0], wg, xA.x); fma2(a2[1], wg, xA.y); fma2(a2[2], wg, xB.x); fma2(a2[3], wg, xB.y);
            fma2(a3[0], wo, xA.x); fma2(a3[1], wo, xA.y); fma2(a3[2], wo, xB.x); fma2(a3[3], wo, xB.y);
        }
        // hidden GEMM layer 0
        gemm64s(wHh0, h0p, u, pb, a0, a1, a2, a3);

        ull hn[NP];
        lstm_update(a0, a1, a2, a3, c0, hn);

        __syncthreads();   // sync1: all reads of old h0 done
#pragma unroll
        for (int p = 0; p < NP; p++) h0p[u * PADP + pb + p] = hn[p];
        __syncthreads();   // sync2: new h0 visible

        // prefetch next timestep's x slice into L2 (28 x 128B lines)
        if (t + 1 < T_STEPS && tid < 2 * IN_F) {
            const char* pf = (const char*)(g_xT + (size_t)((t + 1) * IN_F + (tid >> 1)) * 8192 + b0)
                             + (tid & 1) * 128;
            asm volatile("prefetch.global.L2 [%0];" :: "l"(pf));
        }

        // ================= layer 1 =================
#pragma unroll
        for (int p = 0; p < NP; p++) { a0[p] = bp1[0]; a1[p] = bp1[1]; a2[p] = bp1[2]; a3[p] = bp1[3]; }
        gemm64s(wIh1, h0p, u, pb, a0, a1, a2, a3);   // input = new h0
        gemm64s(wHh1, h1p, u, pb, a0, a1, a2, a3);   // recurrent = old h1

        lstm_update(a0, a1, a2, a3, c1, hn);

        __syncthreads();   // sync3: all reads of old h1 done (write->next-read
                           // ordering covered by sync1/sync2 of the next step)
#pragma unroll
        for (int p = 0; p < NP; p++) h1p[u * PADP + pb + p] = hn[p];
    }
    __syncthreads();       // final h1 visible for FC head

    // ================= FC head =================
    // z[u][b] = relu(sum_k h1[b][k] * w_fc1[u][k] + b_fc1[u]); reuse h0 buffer as z
    {
        ull z[NP];
        float bb = b_fc1[u];
#pragma unroll
        for (int p = 0; p < NP; p++) z[p] = pk(bb, bb);
#pragma unroll 8
        for (int k = 0; k < HID; k++) {
            float w = w_fc1[u * HID + k];
            ull w2 = pk(w, w);
            ulonglong2 hA = *(const ulonglong2*)(h1p + k * PADP + pb);
            ulonglong2 hB = *(const ulonglong2*)(h1p + k * PADP + pb + 2);
            fma2(z[0], w2, hA.x); fma2(z[1], w2, hA.y);
            fma2(z[2], w2, hB.x); fma2(z[3], w2, hB.y);
        }
        __syncthreads();   // everyone done reading h1 before overwriting h0-as-z
#pragma unroll
        for (int p = 0; p < NP; p++) {
            float2 zz = upk(z[p]);
            zz.x = fmaxf(zz.x, 0.0f);
            zz.y = fmaxf(zz.y, 0.0f);
            h0p[u * PADP + pb + p] = pk(zz.x, zz.y);
        }
    }
    __syncthreads();

    // out[b][c] = sum_k z[k][b] * w_fc2[c][k] + b_fc2[c]
    if (tid < 128) {
        int b = tid & 63, c = tid >> 6;
        float acc = b_fc2[c];
#pragma unroll 8
        for (int k = 0; k < HID; k++) acc += sm[OFF_H0 + k * PADF + b] * w_fc2[c * HID + k];
        out[(size_t)(b0 + b) * 2 + c] = acc;
    }
}

extern "C" void kernel_launch(void* const* d_in, const int* in_sizes, int n_in,
                              void* d_out, int out_size) {
    const float* x     = (const float*)d_in[0];
    const float* w_ih0 = (const float*)d_in[1];
    const float* w_hh0 = (const float*)d_in[2];
    const float* b_ih0 = (const float*)d_in[3];
    const float* b_hh0 = (const float*)d_in[4];
    const float* w_ih1 = (const float*)d_in[5];
    const float* w_hh1 = (const float*)d_in[6];
    const float* b_ih1 = (const float*)d_in[7];
    const float* b_hh1 = (const float*)d_in[8];
    const float* w_fc1 = (const float*)d_in[9];
    const float* b_fc1 = (const float*)d_in[10];
    const float* w_fc2 = (const float*)d_in[11];
    const float* b_fc2 = (const float*)d_in[12];
    float* out = (float*)d_out;

    cudaFuncSetAttribute(lstm_fused_kernel,
                         cudaFuncAttributeMaxDynamicSharedMemorySize, SMEM_BYTES);

    pack_wih0_kernel<<<1, IN_F * HID>>>(w_ih0);
    {
        dim3 tb(32, 32);
        dim3 tg((T_STEPS * IN_F) / 32, 8192 / 32);   // 112 x 256
        transpose_x_kernel<<<tg, tb>>>(x);
    }
    lstm_fused_kernel<<<NGRID, NTH, SMEM_BYTES>>>(
        w_hh0, b_ih0, b_hh0,
        w_ih1, w_hh1, b_ih1, b_hh1,
        w_fc1, b_fc1, w_fc2, b_fc2, out);
}

// round 11
// speedup vs baseline: 1.4671x; 1.1116x over previous
#include <cuda_runtime.h>

// MediumLSTM: 2-layer LSTM (I=14, H=64, T=256, B=8192) + FC(64->64 relu)->FC(64->2)
// R11 = R10 resubmit (four acquisition timeouts; never ran).
// Named-barrier group sync: data sharing is block-diagonal in batch group
// (64 threads = 2 warps per group), so the 3 per-timestep barriers are
// bar.sync(bg,64) instead of CTA-wide __syncthreads -> groups drift freely,
// overlapping MUFU bursts with other groups' FMAs.
// All three recurrent weight matrices gate-packed fp32 in smem (192KB); h0/h1
// single-buffered (16B-aligned rows, merged LDS.128). w_ih0 packed in global
// (L1-hot); x pre-transposed [t][i][b], broadcast LDG.128 + L2 prefetch (t+2).
// Batch pairs in fma.rn.f32x2 (exact fp32). Fast sigmoid/tanh via __expf+__fdividef.

#define T_STEPS 256
#define HID     64
#define IN_F    14
#define BT      64      // batch rows per CTA
#define NP      4       // f32x2 pairs per thread (8 batch rows)
#define NTH     512
#define NGRID   128     // 8192 / BT

#define PADP    34      // h row stride in ull pairs (32 pairs + 2 pad) -> 272B, 16B-aligned
#define PADF    68      // same in floats
#define HBUF    (HID * PADF)   // 4352 floats per h buffer

// shared memory float offsets
#define OFF_WHH0 0
#define OFF_WIH1 16384
#define OFF_WHH1 32768
#define OFF_H0   49152
#define OFF_H1   (OFF_H0 + HBUF)
#define SMEM_FLOATS (OFF_H1 + HBUF)        // 57856
#define SMEM_BYTES (SMEM_FLOATS * 4)        // 231,424 B

typedef unsigned long long ull;

// device scratch (allocation-free rule: __device__ globals)
__device__ float  g_xT[(size_t)T_STEPS * IN_F * 8192];   // [t][i][b]
__device__ float4 g_wih0p[IN_F * HID];                   // gate-packed w_ih0

__device__ __forceinline__ ull pk(float a, float b) {
    ull r;
    asm("mov.b64 %0, {%1,%2};" : "=l"(r) : "f"(a), "f"(b));
    return r;
}
__device__ __forceinline__ float2 upk(ull v) {
    float2 r;
    asm("mov.b64 {%0,%1}, %2;" : "=f"(r.x), "=f"(r.y) : "l"(v));
    return r;
}
__device__ __forceinline__ void fma2(ull &d, ull a, ull b) {
    asm("fma.rn.f32x2 %0, %1, %2, %0;" : "+l"(d) : "l"(a), "l"(b));
}
// sigmoid via EX2 + MUFU.RCP (flag-independent fast path)
__device__ __forceinline__ float sigf(float x) {
    return __fdividef(1.0f, 1.0f + __expf(-x));
}
// tanh(x) = 2/(1+exp(-2x)) - 1 ; saturates cleanly at +-1 for large |x|
__device__ __forceinline__ float tanhfast(float x) {
    return fmaf(2.0f, __fdividef(1.0f, 1.0f + __expf(-2.0f * x)), -1.0f);
}

// group barrier: 64 threads (2 warps) sharing one batch group; ids 1..8
#define GBAR(bgid) asm volatile("bar.sync %0, 64;" :: "r"((bgid) + 1) : "memory")

// 64-wide hidden GEMM, weights+h in smem; h loads merged into 2x LDS.128 per k.
__device__ __forceinline__ void gemm64s(const float4* __restrict__ w,
                                        const ull* __restrict__ hv,
                                        int u, int pb,
                                        ull* a0, ull* a1, ull* a2, ull* a3) {
#pragma unroll 8
    for (int k = 0; k < HID; k++) {
        float4 w4 = w[k * 64 + u];
        ull wi = pk(w4.x, w4.x);
        ull wf = pk(w4.y, w4.y);
        ull wg = pk(w4.z, w4.z);
        ull wo = pk(w4.w, w4.w);
        ulonglong2 hA = *(const ulonglong2*)(hv + k * PADP + pb);
        ulonglong2 hB = *(const ulonglong2*)(hv + k * PADP + pb + 2);
        fma2(a0[0], wi, hA.x); fma2(a0[1], wi, hA.y); fma2(a0[2], wi, hB.x); fma2(a0[3], wi, hB.y);
        fma2(a1[0], wf, hA.x); fma2(a1[1], wf, hA.y); fma2(a1[2], wf, hB.x); fma2(a1[3], wf, hB.y);
        fma2(a2[0], wg, hA.x); fma2(a2[1], wg, hA.y); fma2(a2[2], wg, hB.x); fma2(a2[3], wg, hB.y);
        fma2(a3[0], wo, hA.x); fma2(a3[1], wo, hA.y); fma2(a3[2], wo, hB.x); fma2(a3[3], wo, hB.y);
    }
}

__device__ __forceinline__ void lstm_update(const ull* a0, const ull* a1,
                                            const ull* a2, const ull* a3,
                                            ull* cst, ull* hn) {
#pragma unroll
    for (int p = 0; p < NP; p++) {
        float2 gi = upk(a0[p]);
        float2 gf = upk(a1[p]);
        float2 gg = upk(a2[p]);
        float2 go = upk(a3[p]);
        float2 cc = upk(cst[p]);
        cc.x = sigf(gf.x) * cc.x + sigf(gi.x) * tanhfast(gg.x);
        cc.y = sigf(gf.y) * cc.y + sigf(gi.y) * tanhfast(gg.y);
        cst[p] = pk(cc.x, cc.y);
        hn[p] = pk(sigf(go.x) * tanhfast(cc.x), sigf(go.y) * tanhfast(cc.y));
    }
}

// ---------------- pre-kernels ----------------
__global__ void pack_wih0_kernel(const float* __restrict__ w_ih0) {
    int n = blockIdx.x * blockDim.x + threadIdx.x;   // 0..895 : i*64 + u
    if (n < IN_F * HID) {
        int i = n >> 6, u = n & 63;
        float4 v;
        v.x = w_ih0[(0 * 64 + u) * IN_F + i];
        v.y = w_ih0[(1 * 64 + u) * IN_F + i];
        v.z = w_ih0[(2 * 64 + u) * IN_F + i];
        v.w = w_ih0[(3 * 64 + u) * IN_F + i];
        g_wih0p[i * 64 + u] = v;
    }
}

// x[b][ti] -> g_xT[ti][b], ti = t*14+i ; 3584 x 8192 transpose
__global__ void transpose_x_kernel(const float* __restrict__ x) {
    __shared__ float tile[32][33];
    int ti0 = blockIdx.x * 32;
    int b0  = blockIdx.y * 32;
    tile[threadIdx.y][threadIdx.x] =
        x[(size_t)(b0 + threadIdx.y) * (T_STEPS * IN_F) + ti0 + threadIdx.x];
    __syncthreads();
    g_xT[(size_t)(ti0 + threadIdx.y) * 8192 + b0 + threadIdx.x] =
        tile[threadIdx.x][threadIdx.y];
}

// ---------------- main fused kernel ----------------
__global__ void __launch_bounds__(NTH, 1)
lstm_fused_kernel(const float* __restrict__ w_hh0,
                  const float* __restrict__ b_ih0, const float* __restrict__ b_hh0,
                  const float* __restrict__ w_ih1, const float* __restrict__ w_hh1,
                  const float* __restrict__ b_ih1, const float* __restrict__ b_hh1,
                  const float* __restrict__ w_fc1, const float* __restrict__ b_fc1,
                  const float* __restrict__ w_fc2, const float* __restrict__ b_fc2,
                  float* __restrict__ out) {
    extern __shared__ float sm[];
    const int tid = threadIdx.x;
    const int u  = tid & 63;   // hidden unit owned by this thread
    const int bg = tid >> 6;   // batch group (0..7), 8 rows each; 2-warp sync group
    const int pb = bg * NP;    // pair base within a padded row
    const int b0 = blockIdx.x * BT;

    // ---- weights -> smem, transposed + gate-packed: Wp[k][u] = {Wi,Wf,Wg,Wo} at col k
    for (int n = tid; n < 256 * 64; n += NTH) {
        int j = n >> 6, k = n & 63;
        int g = j >> 6, uu = j & 63;
        int dst = (k * 64 + uu) * 4 + g;
        sm[OFF_WHH0 + dst] = w_hh0[n];
        sm[OFF_WIH1 + dst] = w_ih1[n];
        sm[OFF_WHH1 + dst] = w_hh1[n];
    }
    // zero h0/h1 state (contiguous region)
    for (int n = tid; n < 2 * HBUF; n += NTH) sm[OFF_H0 + n] = 0.0f;

    // biases (per-thread, per-gate), packed once
    ull bp0[4], bp1[4];
#pragma unroll
    for (int g = 0; g < 4; g++) {
        float v0 = b_ih0[g * 64 + u] + b_hh0[g * 64 + u];
        float v1 = b_ih1[g * 64 + u] + b_hh1[g * 64 + u];
        bp0[g] = pk(v0, v0);
        bp1[g] = pk(v1, v1);
    }
    __syncthreads();   // CTA-wide: weights + zeroed state visible to all

    ull* h0p = (ull*)(sm + OFF_H0);
    ull* h1p = (ull*)(sm + OFF_H1);
    const float4* wHh0 = (const float4*)(sm + OFF_WHH0);
    const float4* wIh1 = (const float4*)(sm + OFF_WIH1);
    const float4* wHh1 = (const float4*)(sm + OFF_WHH1);

    ull c0[NP], c1[NP];
#pragma unroll
    for (int p = 0; p < NP; p++) { c0[p] = 0ull; c1[p] = 0ull; }

    for (int t = 0; t < T_STEPS; t++) {
        // ================= layer 0 =================
        ull a0[NP], a1[NP], a2[NP], a3[NP];
#pragma unroll
        for (int p = 0; p < NP; p++) { a0[p] = bp0[0]; a1[p] = bp0[1]; a2[p] = bp0[2]; a3[p] = bp0[3]; }

        // input GEMM (14-wide): w from packed global (L1-hot), x from transposed
        // layout (broadcast LDG.128, streamed; prefetched two steps ahead)
#pragma unroll
        for (int i = 0; i < IN_F; i++) {
            float4 w4 = __ldg(&g_wih0p[i * 64 + u]);
            const ull* xrow = (const ull*)(g_xT + (size_t)(t * IN_F + i) * 8192 + b0);
            ull wi = pk(w4.x, w4.x);
            ull wf = pk(w4.y, w4.y);
            ull wg = pk(w4.z, w4.z);
            ull wo = pk(w4.w, w4.w);
            ulonglong2 xA = *(const ulonglong2*)(xrow + pb);
            ulonglong2 xB = *(const ulonglong2*)(xrow + pb + 2);
            fma2(a0[0], wi, xA.x); fma2(a0[1], wi, xA.y); fma2(a0[2], wi, xB.x); fma2(a0[3], wi, xB.y);
            fma2(a1[0], wf, xA.x); fma2(a1[1], wf, xA.y); fma2(a1[2], wf, xB.x); fma2(a1[3], wf, xB.y);
            fma2(a2[0], wg, xA.x); fma2(a2[1], wg, xA.y); fma2(a2[2], wg, xB.x); fma2(a2[3], wg, xB.y);
            fma2(a3[0], wo, xA.x); fma2(a3[1], wo, xA.y); fma2(a3[2], wo, xB.x); fma2(a3[3], wo, xB.y);
        }
        // hidden GEMM layer 0
        gemm64s(wHh0, h0p, u, pb, a0, a1, a2, a3);

        ull hn[NP];
        lstm_update(a0, a1, a2, a3, c0, hn);

        GBAR(bg);          // group sync1: group's reads of old h0 columns done
#pragma unroll
        for (int p = 0; p < NP; p++) h0p[u * PADP + pb + p] = hn[p];
        GBAR(bg);          // group sync2: new h0 columns visible within group

        // prefetch x slice two steps ahead into L2 (28 x 128B lines)
        if (t + 2 < T_STEPS && tid < 2 * IN_F) {
            const char* pf = (const char*)(g_xT + (size_t)((t + 2) * IN_F + (tid >> 1)) * 8192 + b0)
                             + (tid & 1) * 128;
            asm volatile("prefetch.global.L2 [%0];" :: "l"(pf));
        }

        // ================= layer 1 =================
#pragma unroll
        for (int p = 0; p < NP; p++) { a0[p] = bp1[0]; a1[p] = bp1[1]; a2[p] = bp1[2]; a3[p] = bp1[3]; }
        gemm64s(wIh1, h0p, u, pb, a0, a1, a2, a3);   // input = new h0
        gemm64s(wHh1, h1p, u, pb, a0, a1, a2, a3);   // recurrent = old h1

        lstm_update(a0, a1, a2, a3, c1, hn);

        GBAR(bg);          // group sync3: group's reads of old h1 columns done
#pragma unroll
        for (int p = 0; p < NP; p++) h1p[u * PADP + pb + p] = hn[p];
        // write->next-read ordering covered by sync1/sync2 of the next step
    }
    __syncthreads();       // CTA-wide: final h1 visible for FC head

    // ================= FC head =================
    // z[u][b] = relu(sum_k h1[b][k] * w_fc1[u][k] + b_fc1[u]); reuse h0 buffer as z
    {
        ull z[NP];
        float bb = b_fc1[u];
#pragma unroll
        for (int p = 0; p < NP; p++) z[p] = pk(bb, bb);
#pragma unroll 8
        for (int k = 0; k < HID; k++) {
            float w = w_fc1[u * HID + k];
            ull w2 = pk(w, w);
            ulonglong2 hA = *(const ulonglong2*)(h1p + k * PADP + pb);
            ulonglong2 hB = *(const ulonglong2*)(h1p + k * PADP + pb + 2);
            fma2(z[0], w2, hA.x); fma2(z[1], w2, hA.y);
            fma2(z[2], w2, hB.x); fma2(z[3], w2, hB.y);
        }
        __syncthreads();   // everyone done reading h1 before overwriting h0-as-z
#pragma unroll
        for (int p = 0; p < NP; p++) {
            float2 zz = upk(z[p]);
            zz.x = fmaxf(zz.x, 0.0f);
            zz.y = fmaxf(zz.y, 0.0f);
            h0p[u * PADP + pb + p] = pk(zz.x, zz.y);
        }
    }
    __syncthreads();

    // out[b][c] = sum_k z[k][b] * w_fc2[c][k] + b_fc2[c]
    if (tid < 128) {
        int b = tid & 63, c = tid >> 6;
        float acc = b_fc2[c];
#pragma unroll 8
        for (int k = 0; k < HID; k++) acc += sm[OFF_H0 + k * PADF + b] * w_fc2[c * HID + k];
        out[(size_t)(b0 + b) * 2 + c] = acc;
    }
}

extern "C" void kernel_launch(void* const* d_in, const int* in_sizes, int n_in,
                              void* d_out, int out_size) {
    const float* x     = (const float*)d_in[0];
    const float* w_ih0 = (const float*)d_in[1];
    const float* w_hh0 = (const float*)d_in[2];
    const float* b_ih0 = (const float*)d_in[3];
    const float* b_hh0 = (const float*)d_in[4];
    const float* w_ih1 = (const float*)d_in[5];
    const float* w_hh1 = (const float*)d_in[6];
    const float* b_ih1 = (const float*)d_in[7];
    const float* b_hh1 = (const float*)d_in[8];
    const float* w_fc1 = (const float*)d_in[9];
    const float* b_fc1 = (const float*)d_in[10];
    const float* w_fc2 = (const float*)d_in[11];
    const float* b_fc2 = (const float*)d_in[12];
    float* out = (float*)d_out;

    cudaFuncSetAttribute(lstm_fused_kernel,
                         cudaFuncAttributeMaxDynamicSharedMemorySize, SMEM_BYTES);

    pack_wih0_kernel<<<2, 448>>>(w_ih0);
    {
        dim3 tb(32, 32);
        dim3 tg((T_STEPS * IN_F) / 32, 8192 / 32);   // 112 x 256
        transpose_x_kernel<<<tg, tb>>>(x);
    }
    lstm_fused_kernel<<<NGRID, NTH, SMEM_BYTES>>>(
        w_hh0, b_ih0, b_hh0,
        w_ih1, w_hh1, b_ih1, b_hh1,
        w_fc1, b_fc1, w_fc2, b_fc2, out);
}